// round 6
// baseline (speedup 1.0000x reference)
#include <cuda_runtime.h>

// x: (B=64, NU=32, IC=256, UNIT=128) fp32, contiguous.
// Reference reinterprets flat buffer as (B, IC, NU, UNIT):
//   u_hat[b,i,j,u] = x_flat[b*1048576 + i*4096 + j*128 + u]
// s[b,j,u] = (1/256) * sum_i u_hat[b,i,j,u]; then squash over u (128 elems).
// Output: (B, NU, UNIT) = 262144 fp32.
//
// R6: two adjacent j-columns per block -> each warp touches 1KB contiguous
// per row (2 adjacent 512B float4 requests), doubling per-request HBM row
// locality vs R5 (which won 45.1->43.7 by making the live window 4
// consecutive rows). 1024 blocks x 128 threads; warps i-interleaved
// (i = warp + 4k) so the block's live window is 4 consecutive rows x 1KB.
// Per-warp MLP = 16 in-flight LDG.128. Epilogue: warp 0 squashes j0,
// warp 1 squashes j1 (parallel). __ldcs: read-once streaming.

static constexpr int IC      = 256;
static constexpr int BLOCKS  = 64 * 16;        // B * NU/2 = 1024
static constexpr int STRIDE4 = 4096 / 4;       // i-stride in float4 units
static constexpr int THREADS = 128;            // 4 warps/block
static constexpr int IC_PER_W = IC / 4;        // 64 rows per warp

__global__ __launch_bounds__(THREADS, 12)
void capsule_squash_kernel(const float4* __restrict__ x4,
                           float4* __restrict__ out4) {
    const int warp = threadIdx.x >> 5;
    const int lane = threadIdx.x & 31;

    const int b  = blockIdx.x >> 4;            // 64 b values
    const int jp = blockIdx.x & 15;            // j pair: j0=2*jp, j1=2*jp+1
    // float4 base for (b, row=warp, column j0, lane)
    const int base4 = b * (1048576 / 4) + jp * (256 / 4) + lane
                    + warp * STRIDE4;

    float4 s0 = make_float4(0.f, 0.f, 0.f, 0.f);
    float4 s1 = make_float4(0.f, 0.f, 0.f, 0.f);
#pragma unroll 8
    for (int k = 0; k < IC_PER_W; k++) {
        const float4* p = &x4[base4 + k * (4 * STRIDE4)];
        float4 v0 = __ldcs(p);                 // column j0: 512B across warp
        float4 v1 = __ldcs(p + 32);            // column j1: adjacent 512B
        s0.x += v0.x; s0.y += v0.y; s0.z += v0.z; s0.w += v0.w;
        s1.x += v1.x; s1.y += v1.y; s1.z += v1.z; s1.w += v1.w;
    }

    __shared__ float4 part[4][2][32];
    part[warp][0][lane] = s0;
    part[warp][1][lane] = s1;
    __syncthreads();

    if (warp < 2) {                            // warp 0 -> j0, warp 1 -> j1
        float4 t = part[0][warp][lane];
#pragma unroll
        for (int w = 1; w < 4; w++) {
            float4 p = part[w][warp][lane];
            t.x += p.x; t.y += p.y; t.z += p.z; t.w += p.w;
        }
        const float c = 1.0f / 256.0f;
        t.x *= c; t.y *= c; t.z *= c; t.w *= c;

        // mag_sq over the 128-element unit dim (warp-wide)
        float sq = t.x * t.x + t.y * t.y + t.z * t.z + t.w * t.w;
#pragma unroll
        for (int off = 16; off > 0; off >>= 1)
            sq += __shfl_xor_sync(0xffffffffu, sq, off);

        const float mag   = sqrtf(sq);
        const float scale = sq / (1.0f + sq) / (mag + 1e-5f);

        const int g = (blockIdx.x << 1) + warp;    // global group = b*32 + j
        out4[g * 32 + lane] = make_float4(t.x * scale, t.y * scale,
                                          t.z * scale, t.w * scale);
    }
}

extern "C" void kernel_launch(void* const* d_in, const int* in_sizes, int n_in,
                              void* d_out, int out_size) {
    const float4* x4 = (const float4*)d_in[0];
    float4* out4 = (float4*)d_out;
    capsule_squash_kernel<<<BLOCKS, THREADS>>>(x4, out4);
}